// round 8
// baseline (speedup 1.0000x reference)
#include <cuda_runtime.h>

// SMFNet B=2,N=8192,D=64,DV=64,M=3 — chord mask = diag + superdiag(wrap).
// out = S · V0 ;  V0 = X@Wg + bg ; S = product of three 2-banded chord mats:
//   out[i] = w0 V0[i] + w1 V0[i+1] + w2 V0[i+2] + w3 V0[i+3]   (wrap)
//   Am_j = X[j]·Wf[m][:,j] + bf[m][j],  Cm_j = X[j]·Wf[m][:,j+1] + bf[m][j+1]
// R8: X staged as duplicated f32x2 pairs -> packed-FMA GEMM with no packing
// movs in the inner loop; A/C dots fully unrolled for MLP.

#define Bc   2
#define Nc   8192
#define Dc   64
#define TROWS 16           // output rows per CTA -> 512 CTAs
#define XR    19           // staged rows per batch (TROWS+3)
#define RS    (2*XR)       // 38 row-slots
#define PD2   66           // Xd row stride in u64 (528B, 16B-aligned, even)
#define VPAD  68           // Vs row stride in floats
#define ACW   20
#define NTHREADS 256

typedef unsigned long long u64;

// smem layout
// Xd: RS*PD2 u64  = 2508 u64  = 20064 B
// Vs: RS*VPAD f32 = 2584 f32  = 10336 B
// As/Cs: 6*ACW each
#define XD_U64S   (RS*PD2)
#define OFF_VS    (XD_U64S*2)            // in floats
#define OFF_AS    (OFF_VS + RS*VPAD)
#define OFF_CS    (OFF_AS + 6*ACW)
#define SMEM_FLOATS (OFF_CS + 6*ACW)
#define SMEM_BYTES  (SMEM_FLOATS * 4)

__device__ __forceinline__ u64 pack2(float x, float y) {
    u64 r;
    asm("mov.b64 %0, {%1, %2};" : "=l"(r) : "f"(x), "f"(y));
    return r;
}
__device__ __forceinline__ void fma2(u64& d, u64 a, u64 b) {
    asm("fma.rn.f32x2 %0, %1, %2, %3;" : "=l"(d) : "l"(a), "l"(b), "l"(d));
}

__global__ __launch_bounds__(NTHREADS, 4)
void smf_fused_kernel(const float* __restrict__ X,
                      const float* __restrict__ Wg,
                      const float* __restrict__ bg,
                      const float* __restrict__ Wf,
                      const float* __restrict__ bf,
                      float* __restrict__ out)
{
    extern __shared__ float sm[];
    u64*   Xd = reinterpret_cast<u64*>(sm);   // [RS][PD2], each = (x,x)
    float* Vs = sm + OFF_VS;                  // [RS][VPAD]
    float* As = sm + OFF_AS;                  // [(b*3+m)*ACW + j]
    float* Cs = sm + OFF_CS;

    const int t  = threadIdx.x;
    const int r0 = blockIdx.x * TROWS;

    // ---- Phase A: stage X rows r0..r0+18 (wrap), both batches, duplicated ----
    {
        const float4* X4 = reinterpret_cast<const float4*>(X);
        #pragma unroll
        for (int idx = t; idx < RS * 16; idx += NTHREADS) {
            int rs = idx >> 4, q = idx & 15;
            int b  = rs >= XR;
            int j  = rs - b * XR;
            int gi = (r0 + j) & (Nc - 1);
            float4 v = X4[((size_t)b * Nc + gi) * 16 + q];
            u64* dst = Xd + rs * PD2 + q * 4;
            dst[0] = pack2(v.x, v.x);
            dst[1] = pack2(v.y, v.y);
            dst[2] = pack2(v.z, v.z);
            dst[3] = pack2(v.w, v.w);
        }
    }
    __syncthreads();

    // ---- Phase B1: A/C dots (216 tasks), direct LDG, full unroll for MLP ----
    if (t < 216) {
        const int j = t % 18;
        const int g = t / 18;           // 0..11
        const int isC = g & 1;
        const int m   = (g >> 1) % 3;
        const int b   = g / 6;
        const int gic = (r0 + j + isC) & (Nc - 1);
        const float* wp = Wf + (size_t)m * Dc * Nc + gic;
        const float* xp = reinterpret_cast<const float*>(Xd + (b * XR + j) * PD2);
        float acc = 0.f;
        #pragma unroll
        for (int d = 0; d < Dc; d++)
            acc = fmaf(xp[2 * d], __ldg(wp + (size_t)d * Nc), acc);
        acc += __ldg(bf + m * Nc + gic);
        (isC ? Cs : As)[(b * 3 + m) * ACW + j] = acc;
    }

    // ---- Phase B2: GEMM V0 = X@Wg + bg over 38 row-slots ----
    // thread: col quad e0 = 4*(t&15); rows rg, rg+16, (+32 for rg<6)
    {
        const int e0 = (t & 15) * 4;
        const int rg = t >> 4;            // 0..15
        const bool has3 = (rg < RS - 32); // rows 32..37

        float4 bgq = __ldg(reinterpret_cast<const float4*>(bg + e0));
        u64 b01 = pack2(bgq.x, bgq.y), b23 = pack2(bgq.z, bgq.w);
        u64 aA01 = b01, aA23 = b23;
        u64 aB01 = b01, aB23 = b23;
        u64 aC01 = b01, aC23 = b23;

        const ulonglong2* pa = reinterpret_cast<const ulonglong2*>(Xd + rg * PD2);
        const ulonglong2* pb = reinterpret_cast<const ulonglong2*>(Xd + (rg + 16) * PD2);
        const ulonglong2* pc = reinterpret_cast<const ulonglong2*>(Xd + ((rg + 32) & 63) * PD2);
        const ulonglong2* wgp = reinterpret_cast<const ulonglong2*>(Wg + e0);

        #pragma unroll 8
        for (int h = 0; h < Dc / 2; h++) {          // d = 2h, 2h+1
            ulonglong2 xa = pa[h];                  // (dup x_d, dup x_{d+1})
            ulonglong2 xb = pb[h];
            ulonglong2 w0 = __ldg(wgp + h * 32);        // row d   : (w01, w23)
            ulonglong2 w1 = __ldg(wgp + h * 32 + 16);   // row d+1
            fma2(aA01, xa.x, w0.x);  fma2(aA23, xa.x, w0.y);
            fma2(aA01, xa.y, w1.x);  fma2(aA23, xa.y, w1.y);
            fma2(aB01, xb.x, w0.x);  fma2(aB23, xb.x, w0.y);
            fma2(aB01, xb.y, w1.x);  fma2(aB23, xb.y, w1.y);
            if (has3) {
                ulonglong2 xc = pc[h];
                fma2(aC01, xc.x, w0.x);  fma2(aC23, xc.x, w0.y);
                fma2(aC01, xc.y, w1.x);  fma2(aC23, xc.y, w1.y);
            }
        }
        // store packed accumulators straight to Vs (STS.64, no unpack)
        u64* v0 = reinterpret_cast<u64*>(&Vs[rg * VPAD + e0]);
        v0[0] = aA01;  v0[1] = aA23;
        u64* v1 = reinterpret_cast<u64*>(&Vs[(rg + 16) * VPAD + e0]);
        v1[0] = aB01;  v1[1] = aB23;
        if (has3) {
            u64* v2 = reinterpret_cast<u64*>(&Vs[(rg + 32) * VPAD + e0]);
            v2[0] = aC01;  v2[1] = aC23;
        }
    }
    __syncthreads();

    // ---- Phase C: inline weights + 4-tap combine + store ----
    {
        const int e0 = (t & 15) * 4;
        const int jr = t >> 4;
        #pragma unroll
        for (int b = 0; b < Bc; b++) {
            const float* A1 = &As[(b * 3 + 0) * ACW];
            const float* C1 = &Cs[(b * 3 + 0) * ACW];
            const float* A2 = &As[(b * 3 + 1) * ACW];
            const float* C2 = &Cs[(b * 3 + 1) * ACW];
            const float* A3p = &As[(b * 3 + 2) * ACW];
            const float* C3p = &Cs[(b * 3 + 2) * ACW];
            float A1i = A1[jr], A1i1 = A1[jr + 1], A1i2 = A1[jr + 2];
            float C1i = C1[jr], C1i1 = C1[jr + 1], C1i2 = C1[jr + 2];
            float A2i = A2[jr], A2i1 = A2[jr + 1];
            float C2i = C2[jr], C2i1 = C2[jr + 1];
            float A3  = A3p[jr], C3 = C3p[jr];
            float w0 = A3 * A2i * A1i;
            float w1 = A3 * (A2i * C1i + C2i * A1i1) + C3 * A2i1 * A1i1;
            float w2 = A3 * C2i * C1i1 + C3 * (A2i1 * C1i1 + C2i1 * A1i2);
            float w3 = C3 * C2i1 * C1i2;

            const float* vb = &Vs[(b * XR + jr) * VPAD + e0];
            float4 p0 = *reinterpret_cast<const float4*>(vb);
            float4 p1 = *reinterpret_cast<const float4*>(vb + VPAD);
            float4 p2 = *reinterpret_cast<const float4*>(vb + 2 * VPAD);
            float4 p3 = *reinterpret_cast<const float4*>(vb + 3 * VPAD);

            float4 o;
            o.x = w0 * p0.x + w1 * p1.x + w2 * p2.x + w3 * p3.x;
            o.y = w0 * p0.y + w1 * p1.y + w2 * p2.y + w3 * p3.y;
            o.z = w0 * p0.z + w1 * p1.z + w2 * p2.z + w3 * p3.z;
            o.w = w0 * p0.w + w1 * p1.w + w2 * p2.w + w3 * p3.w;

            const int gi = r0 + jr;
            *reinterpret_cast<float4*>(&out[((size_t)b * Nc + gi) * 64 + e0]) = o;
        }
    }
}

extern "C" void kernel_launch(void* const* d_in, const int* in_sizes, int n_in,
                              void* d_out, int out_size)
{
    const float* X  = (const float*)d_in[0];   // (2, 8192, 64)
    const float* Wg = (const float*)d_in[1];   // (64, 64)
    const float* bg = (const float*)d_in[2];   // (64,)
    const float* Wf = (const float*)d_in[3];   // (3, 64, 8192)
    const float* bf = (const float*)d_in[4];   // (3, 8192)
    float* out = (float*)d_out;                // (2, 8192, 64)

    cudaFuncSetAttribute(smf_fused_kernel,
                         cudaFuncAttributeMaxDynamicSharedMemorySize, SMEM_BYTES);

    dim3 grid(Nc / TROWS, 1);                  // 512 CTAs
    smf_fused_kernel<<<grid, NTHREADS, SMEM_BYTES>>>(X, Wg, bg, Wf, bf, out);
}